// round 2
// baseline (speedup 1.0000x reference)
#include <cuda_runtime.h>
#include <math.h>

#define B_ 1024
#define I_ 256
#define O_ 256
#define K_ 128
#define BT 4   // batch rows per CTA in main kernel

// Static device scratch (allocation-free rule: __device__ globals only)
__device__ float  g_csT[(size_t)I_ * K_ * O_];  // [i][k][o], scale folded in (32 MB)
__device__ float  g_wt[I_ * O_];                // [i][o] transposed base weight
__device__ float4 g_meta[B_ * I_];              // {offL bits, offR bits, frac, silu}

// ---------------------------------------------------------------------------
// Pack: per (b,i) compute tanh/silu/bin/frac and absolute gather offsets.
// ---------------------------------------------------------------------------
__global__ void pack_kernel(const float* __restrict__ x) {
    int t = blockIdx.x * blockDim.x + threadIdx.x;
    if (t >= B_ * I_) return;
    int i = t & (I_ - 1);

    float xv = x[t];
    float p = tanhf(xv);
    float silu = p / (1.0f + expf(-p));
    float c = fminf(fmaxf(p, -1.0f), 1.0f);
    const float step = 2.0f / 127.0f;          // (DMAX-DMIN)/(K-1), fp32-rounded like ref
    float scaled = (c + 1.0f) / step;
    int l = (int)floorf(scaled);
    l = max(0, min(l, K_ - 1));
    int r = min(l + 1, K_ - 1);
    float frac = scaled - (float)l;

    int offL = i * (K_ * O_) + l * O_;
    int offR = i * (K_ * O_) + r * O_;

    float4 m;
    m.x = __int_as_float(offL);
    m.y = __int_as_float(offR);
    m.z = frac;
    m.w = silu;
    g_meta[t] = m;
}

// ---------------------------------------------------------------------------
// Transpose coeff (O,I,K) -> csT (I,K,O), folding in spline_scale[o,i].
// Per fixed i this is a 32x32-tiled (O x K) -> (K x O) transpose.
// block (32,8), grid (K/32, O/32, I)
// ---------------------------------------------------------------------------
__global__ void transpose_coeff_kernel(const float* __restrict__ coeff,
                                       const float* __restrict__ scale) {
    __shared__ float tile[32][33];
    int i  = blockIdx.z;
    int k0 = blockIdx.x * 32;
    int o0 = blockIdx.y * 32;
    int tx = threadIdx.x, ty = threadIdx.y;

#pragma unroll
    for (int j = 0; j < 32; j += 8) {
        int o = o0 + ty + j;
        float v = coeff[(size_t)o * (I_ * K_) + i * K_ + k0 + tx];  // k-contig: coalesced
        tile[ty + j][tx] = v * scale[o * I_ + i];
    }
    __syncthreads();
#pragma unroll
    for (int j = 0; j < 32; j += 8) {
        int k = k0 + ty + j;
        g_csT[(size_t)i * (K_ * O_) + k * O_ + o0 + tx] = tile[tx][ty + j];  // o-contig
    }
}

// ---------------------------------------------------------------------------
// Transpose base_weight (O,I) -> g_wt (I,O). block (32,8), grid (I/32, O/32)
// ---------------------------------------------------------------------------
__global__ void transpose_w_kernel(const float* __restrict__ w) {
    __shared__ float tile[32][33];
    int i0 = blockIdx.x * 32;
    int o0 = blockIdx.y * 32;
    int tx = threadIdx.x, ty = threadIdx.y;
#pragma unroll
    for (int j = 0; j < 32; j += 8) {
        tile[ty + j][tx] = w[(o0 + ty + j) * I_ + i0 + tx];   // i-contig read
    }
    __syncthreads();
#pragma unroll
    for (int j = 0; j < 32; j += 8) {
        g_wt[(i0 + ty + j) * O_ + o0 + tx] = tile[tx][ty + j]; // o-contig write
    }
}

// ---------------------------------------------------------------------------
// Main: out[b,o] = sum_i [ cL + frac*(cR-cL) + silu*WT[i,o] ] + bias[o]
// 256 threads = full O; BT batch rows per CTA; metadata staged in smem.
// Gathers are warp-coalesced 128B slices of csT rows (L2-resident).
// ---------------------------------------------------------------------------
__global__ __launch_bounds__(256) void kan_main_kernel(const float* __restrict__ bias,
                                                       float* __restrict__ out) {
    __shared__ float4 smeta[BT * I_];   // 16 KB

    int b0 = blockIdx.x * BT;
    int o  = threadIdx.x;

    for (int t = threadIdx.x; t < BT * I_; t += 256) {
        int bb = t >> 8;          // t / I_
        int ii = t & (I_ - 1);
        smeta[t] = g_meta[(b0 + bb) * I_ + ii];
    }
    __syncthreads();

    float acc[BT];
#pragma unroll
    for (int bb = 0; bb < BT; bb++) acc[bb] = 0.0f;

#pragma unroll 2
    for (int i = 0; i < I_; i++) {
        float wrow = g_wt[i * O_ + o];
#pragma unroll
        for (int bb = 0; bb < BT; bb++) {
            float4 m = smeta[bb * I_ + i];                 // LDS.128 broadcast
            float cL = g_csT[__float_as_int(m.x) + o];     // coalesced gather
            float cR = g_csT[__float_as_int(m.y) + o];
            // acc += cL + frac*(cR-cL) + silu*wrow
            acc[bb] = fmaf(m.z, cR - cL, fmaf(m.w, wrow, acc[bb] + cL));
        }
    }

    float bv = bias[o];
#pragma unroll
    for (int bb = 0; bb < BT; bb++) {
        out[(size_t)(b0 + bb) * O_ + o] = acc[bb] + bv;
    }
}

// ---------------------------------------------------------------------------
// kernel_launch: graph-capturable, allocation-free, default stream.
// Inputs (metadata order): x, base_weight, spline_coefficients, spline_scale, bias
// ---------------------------------------------------------------------------
extern "C" void kernel_launch(void* const* d_in, const int* in_sizes, int n_in,
                              void* d_out, int out_size) {
    const float* x     = (const float*)d_in[0];
    const float* w     = (const float*)d_in[1];
    const float* coeff = (const float*)d_in[2];
    const float* scale = (const float*)d_in[3];
    const float* bias  = (const float*)d_in[4];
    float* out = (float*)d_out;

    pack_kernel<<<(B_ * I_ + 255) / 256, 256>>>(x);
    transpose_coeff_kernel<<<dim3(K_ / 32, O_ / 32, I_), dim3(32, 8)>>>(coeff, scale);
    transpose_w_kernel<<<dim3(I_ / 32, O_ / 32), dim3(32, 8)>>>(w);
    kan_main_kernel<<<B_ / BT, 256>>>(bias, out);
}

// round 4
// speedup vs baseline: 1.8829x; 1.8829x over previous
#include <cuda_runtime.h>
#include <math.h>

#define B_ 1024
#define I_ 256
#define O_ 256
#define K_ 128
#define BT 4          // batch rows per CTA in main kernel
#define ISPLIT 4      // i-dimension split factor
#define ICHUNK (I_ / ISPLIT)   // 64 i-values per CTA

// Static device scratch (allocation-free rule: __device__ globals only)
__device__ float  g_csT[(size_t)I_ * K_ * O_];        // [i][k][o], scale folded in (32 MB)
__device__ float  g_wt[I_ * O_];                      // [i][o] transposed base weight
__device__ float4 g_meta[B_ * I_];                    // {offL bits, offR bits, frac, silu}
__device__ float  g_part[ISPLIT][B_ * O_];            // partial sums (4 MB)

// ---------------------------------------------------------------------------
// Pack: per (b,i) compute tanh/silu/bin/frac and absolute gather offsets.
// ---------------------------------------------------------------------------
__global__ void pack_kernel(const float* __restrict__ x) {
    int t = blockIdx.x * blockDim.x + threadIdx.x;
    if (t >= B_ * I_) return;
    int i = t & (I_ - 1);

    float xv = x[t];
    float p = tanhf(xv);
    float silu = p / (1.0f + expf(-p));
    float c = fminf(fmaxf(p, -1.0f), 1.0f);
    const float step = 2.0f / 127.0f;
    float scaled = (c + 1.0f) / step;
    int l = (int)floorf(scaled);
    l = max(0, min(l, K_ - 1));
    int r = min(l + 1, K_ - 1);
    float frac = scaled - (float)l;

    int offL = i * (K_ * O_) + l * O_;
    int offR = i * (K_ * O_) + r * O_;

    float4 m;
    m.x = __int_as_float(offL);
    m.y = __int_as_float(offR);
    m.z = frac;
    m.w = silu;
    g_meta[t] = m;
}

// ---------------------------------------------------------------------------
// Transpose coeff (O,I,K) -> csT (I,K,O), folding in spline_scale[o,i].
// block (32,8), grid (K/32, O/32, I)
// ---------------------------------------------------------------------------
__global__ void transpose_coeff_kernel(const float* __restrict__ coeff,
                                       const float* __restrict__ scale) {
    __shared__ float tile[32][33];
    int i  = blockIdx.z;
    int k0 = blockIdx.x * 32;
    int o0 = blockIdx.y * 32;
    int tx = threadIdx.x, ty = threadIdx.y;

#pragma unroll
    for (int j = 0; j < 32; j += 8) {
        int o = o0 + ty + j;
        float v = coeff[(size_t)o * (I_ * K_) + i * K_ + k0 + tx];  // k-contig read
        tile[ty + j][tx] = v * scale[o * I_ + i];
    }
    __syncthreads();
#pragma unroll
    for (int j = 0; j < 32; j += 8) {
        int k = k0 + ty + j;
        g_csT[(size_t)i * (K_ * O_) + k * O_ + o0 + tx] = tile[tx][ty + j];  // o-contig write
    }
}

// ---------------------------------------------------------------------------
// Transpose base_weight (O,I) -> g_wt (I,O). block (32,8), grid (I/32, O/32)
// ---------------------------------------------------------------------------
__global__ void transpose_w_kernel(const float* __restrict__ w) {
    __shared__ float tile[32][33];
    int i0 = blockIdx.x * 32;
    int o0 = blockIdx.y * 32;
    int tx = threadIdx.x, ty = threadIdx.y;
#pragma unroll
    for (int j = 0; j < 32; j += 8) {
        tile[ty + j][tx] = w[(o0 + ty + j) * I_ + i0 + tx];
    }
    __syncthreads();
#pragma unroll
    for (int j = 0; j < 32; j += 8) {
        g_wt[(i0 + ty + j) * O_ + o0 + tx] = tile[tx][ty + j];
    }
}

// ---------------------------------------------------------------------------
// Main: partial[b,o] over an i-chunk. grid (B/BT, ISPLIT), block 256 (= O).
// 1024 CTAs -> ~7 CTAs/SM, ~56 warps/SM: hides L2 gather latency.
// ---------------------------------------------------------------------------
__global__ __launch_bounds__(256) void kan_main_kernel() {
    __shared__ float4 smeta[BT * ICHUNK];   // 4 KB

    int b0 = blockIdx.x * BT;
    int i0 = blockIdx.y * ICHUNK;
    int o  = threadIdx.x;

    for (int t = threadIdx.x; t < BT * ICHUNK; t += 256) {
        int bb = t / ICHUNK;
        int ii = t % ICHUNK;
        smeta[t] = g_meta[(b0 + bb) * I_ + i0 + ii];
    }
    __syncthreads();

    float acc[BT];
#pragma unroll
    for (int bb = 0; bb < BT; bb++) acc[bb] = 0.0f;

#pragma unroll 2
    for (int i = 0; i < ICHUNK; i++) {
        float wrow = g_wt[(i0 + i) * O_ + o];
#pragma unroll
        for (int bb = 0; bb < BT; bb++) {
            float4 m = smeta[bb * ICHUNK + i];             // LDS.128 broadcast
            float cL = g_csT[__float_as_int(m.x) + o];     // coalesced 128B/warp gather
            float cR = g_csT[__float_as_int(m.y) + o];
            acc[bb] = fmaf(m.z, cR - cL, fmaf(m.w, wrow, acc[bb] + cL));
        }
    }

#pragma unroll
    for (int bb = 0; bb < BT; bb++) {
        g_part[blockIdx.y][(b0 + bb) * O_ + o] = acc[bb];
    }
}

// ---------------------------------------------------------------------------
// Reduce: out[b,o] = bias[o] + sum_s part[s][b,o]. Deterministic (no atomics).
// ---------------------------------------------------------------------------
__global__ __launch_bounds__(256) void reduce_kernel(const float* __restrict__ bias,
                                                     float* __restrict__ out) {
    int t = blockIdx.x * 256 + threadIdx.x;   // t in [0, B*O)
    float s = bias[t & (O_ - 1)];
#pragma unroll
    for (int p = 0; p < ISPLIT; p++) s += g_part[p][t];
    out[t] = s;
}

// ---------------------------------------------------------------------------
// kernel_launch: graph-capturable, allocation-free, default stream.
// Inputs (metadata order): x, base_weight, spline_coefficients, spline_scale, bias
// ---------------------------------------------------------------------------
extern "C" void kernel_launch(void* const* d_in, const int* in_sizes, int n_in,
                              void* d_out, int out_size) {
    const float* x     = (const float*)d_in[0];
    const float* w     = (const float*)d_in[1];
    const float* coeff = (const float*)d_in[2];
    const float* scale = (const float*)d_in[3];
    const float* bias  = (const float*)d_in[4];
    float* out = (float*)d_out;

    pack_kernel<<<(B_ * I_ + 255) / 256, 256>>>(x);
    transpose_coeff_kernel<<<dim3(K_ / 32, O_ / 32, I_), dim3(32, 8)>>>(coeff, scale);
    transpose_w_kernel<<<dim3(I_ / 32, O_ / 32), dim3(32, 8)>>>(w);
    kan_main_kernel<<<dim3(B_ / BT, ISPLIT), 256>>>();
    reduce_kernel<<<(B_ * O_) / 256, 256>>>(bias, out);
}

// round 6
// speedup vs baseline: 2.0032x; 1.0639x over previous
#include <cuda_runtime.h>
#include <math.h>

#define B_ 1024
#define I_ 256
#define O_ 256
#define K_ 128
#define BT 4          // batch rows per CTA in main kernel
#define ISPLIT 4      // i-dimension split factor
#define ICHUNK (I_ / ISPLIT)   // 64 i-values per CTA

// Static device scratch (allocation-free rule: __device__ globals only)
__device__ float  g_csT[(size_t)I_ * K_ * O_];        // [i][k][o], scale folded in (32 MB)
__device__ float  g_wt[I_ * O_];                      // [i][o] transposed base weight
__device__ float4 g_meta[B_ * I_];                    // {offL bits, offR bits, frac, silu}
__device__ float  g_part[ISPLIT][B_ * O_];            // partial sums (4 MB)

// ---------------------------------------------------------------------------
// Pack: per (b,i) compute tanh/silu/bin/frac and absolute gather offsets.
// ---------------------------------------------------------------------------
__global__ void pack_kernel(const float* __restrict__ x) {
    int t = blockIdx.x * blockDim.x + threadIdx.x;
    if (t >= B_ * I_) return;
    int i = t & (I_ - 1);

    float xv = x[t];
    float p = tanhf(xv);
    float silu = p / (1.0f + expf(-p));
    float c = fminf(fmaxf(p, -1.0f), 1.0f);
    const float step = 2.0f / 127.0f;
    float scaled = (c + 1.0f) / step;
    int l = (int)floorf(scaled);
    l = max(0, min(l, K_ - 1));
    int r = min(l + 1, K_ - 1);
    float frac = scaled - (float)l;

    int offL = i * (K_ * O_) + l * O_;
    int offR = i * (K_ * O_) + r * O_;

    float4 m;
    m.x = __int_as_float(offL);
    m.y = __int_as_float(offR);
    m.z = frac;
    m.w = silu;
    g_meta[t] = m;
}

// ---------------------------------------------------------------------------
// Transpose coeff (O,I,K) -> csT (I,K,O), folding in spline_scale[o,i].
// float4 reads along k. block (8,32): tx -> k-quad, ty -> o within 32-tile.
// Write side: thread (tx,ty) emits k = k0+ty, o-quad = o0 + tx*4.
// grid (K/32, O/32, I)
// ---------------------------------------------------------------------------
__global__ void transpose_coeff_kernel(const float* __restrict__ coeff,
                                       const float* __restrict__ scale) {
    __shared__ float tile[32][33];
    int i  = blockIdx.z;
    int k0 = blockIdx.x * 32;
    int o0 = blockIdx.y * 32;
    int tx = threadIdx.x;   // 0..7
    int ty = threadIdx.y;   // 0..31

    int o = o0 + ty;
    float s = scale[o * I_ + i];
    const float4* src = (const float4*)&coeff[(size_t)o * (I_ * K_) + i * K_ + k0];
    float4 v = src[tx];                         // coalesced 16B loads along k
    tile[ty][tx * 4 + 0] = v.x * s;
    tile[ty][tx * 4 + 1] = v.y * s;
    tile[ty][tx * 4 + 2] = v.z * s;
    tile[ty][tx * 4 + 3] = v.w * s;
    __syncthreads();

    int k = k0 + ty;
    float4 w;
    w.x = tile[tx * 4 + 0][ty];
    w.y = tile[tx * 4 + 1][ty];
    w.z = tile[tx * 4 + 2][ty];
    w.w = tile[tx * 4 + 3][ty];
    *(float4*)&g_csT[(size_t)i * (K_ * O_) + k * O_ + o0 + tx * 4] = w;
}

// ---------------------------------------------------------------------------
// Transpose base_weight (O,I) -> g_wt (I,O). block (32,8), grid (I/32, O/32)
// ---------------------------------------------------------------------------
__global__ void transpose_w_kernel(const float* __restrict__ w) {
    __shared__ float tile[32][33];
    int i0 = blockIdx.x * 32;
    int o0 = blockIdx.y * 32;
    int tx = threadIdx.x, ty = threadIdx.y;
#pragma unroll
    for (int j = 0; j < 32; j += 8) {
        tile[ty + j][tx] = w[(o0 + ty + j) * I_ + i0 + tx];
    }
    __syncthreads();
#pragma unroll
    for (int j = 0; j < 32; j += 8) {
        g_wt[(i0 + ty + j) * O_ + o0 + tx] = tile[tx][ty + j];
    }
}

// ---------------------------------------------------------------------------
// Main: float4 over o. block (64,4): tx -> o-quad, ty -> batch row.
// grid (B/BT, ISPLIT). Per i-step each thread: 3x LDG.128 + 1x LDS.128 + 12 FMA.
// ---------------------------------------------------------------------------
__global__ __launch_bounds__(256) void kan_main_kernel() {
    __shared__ float4 smeta[BT][ICHUNK];   // 4 KB

    int b0 = blockIdx.x * BT;
    int i0 = blockIdx.y * ICHUNK;
    int tx = threadIdx.x;                  // 0..63
    int ty = threadIdx.y;                  // 0..3
    int o4 = tx * 4;

    {
        int t = ty * 64 + tx;              // 0..255 -> one meta each
        int bb = t >> 6;                   // t / ICHUNK
        int ii = t & (ICHUNK - 1);
        smeta[bb][ii] = g_meta[(b0 + bb) * I_ + i0 + ii];
    }
    __syncthreads();

    float4 acc = make_float4(0.f, 0.f, 0.f, 0.f);

#pragma unroll 2
    for (int i = 0; i < ICHUNK; i++) {
        float4 m = smeta[ty][i];                                   // LDS.128 broadcast
        float4 wv = *(const float4*)&g_wt[(i0 + i) * O_ + o4];     // L1-resident
        float4 cL = *(const float4*)&g_csT[__float_as_int(m.x) + o4];
        float4 cR = *(const float4*)&g_csT[__float_as_int(m.y) + o4];
        acc.x = fmaf(m.z, cR.x - cL.x, fmaf(m.w, wv.x, acc.x + cL.x));
        acc.y = fmaf(m.z, cR.y - cL.y, fmaf(m.w, wv.y, acc.y + cL.y));
        acc.z = fmaf(m.z, cR.z - cL.z, fmaf(m.w, wv.z, acc.z + cL.z));
        acc.w = fmaf(m.z, cR.w - cL.w, fmaf(m.w, wv.w, acc.w + cL.w));
    }

    *(float4*)&g_part[blockIdx.y][(b0 + ty) * O_ + o4] = acc;
}

// ---------------------------------------------------------------------------
// Reduce: out[b,o] = bias[o] + sum_s part[s][b,o]. float4, deterministic.
// ---------------------------------------------------------------------------
__global__ __launch_bounds__(256) void reduce_kernel(const float* __restrict__ bias,
                                                     float* __restrict__ out) {
    int q = blockIdx.x * 256 + threadIdx.x;       // float4 index in [0, B*O/4)
    int o4 = (q * 4) & (O_ - 1);
    const float4 b4 = *(const float4*)&bias[o4];
    float4 s = b4;
#pragma unroll
    for (int p = 0; p < ISPLIT; p++) {
        float4 v = *(const float4*)&g_part[p][q * 4];
        s.x += v.x; s.y += v.y; s.z += v.z; s.w += v.w;
    }
    *(float4*)&out[q * 4] = s;
}

// ---------------------------------------------------------------------------
// kernel_launch: graph-capturable, allocation-free, default stream.
// Inputs (metadata order): x, base_weight, spline_coefficients, spline_scale, bias
// ---------------------------------------------------------------------------
extern "C" void kernel_launch(void* const* d_in, const int* in_sizes, int n_in,
                              void* d_out, int out_size) {
    const float* x     = (const float*)d_in[0];
    const float* w     = (const float*)d_in[1];
    const float* coeff = (const float*)d_in[2];
    const float* scale = (const float*)d_in[3];
    const float* bias  = (const float*)d_in[4];
    float* out = (float*)d_out;

    pack_kernel<<<(B_ * I_ + 255) / 256, 256>>>(x);
    transpose_coeff_kernel<<<dim3(K_ / 32, O_ / 32, I_), dim3(8, 32)>>>(coeff, scale);
    transpose_w_kernel<<<dim3(I_ / 32, O_ / 32), dim3(32, 8)>>>(w);
    kan_main_kernel<<<dim3(B_ / BT, ISPLIT), dim3(64, 4)>>>();
    reduce_kernel<<<(B_ * O_) / 1024, 256>>>(bias, out);
}

// round 10
// speedup vs baseline: 2.0958x; 1.0462x over previous
#include <cuda_runtime.h>
#include <math.h>

#define B_ 1024
#define I_ 256
#define O_ 256
#define K_ 128
#define BT 4          // batch rows per CTA in main kernel
#define ISPLIT 4      // i-dimension split factor
#define ICHUNK (I_ / ISPLIT)   // 64 i-values per CTA

// Static device scratch (allocation-free rule: __device__ globals only).
// g_csT padded by O_ floats (zero-initialized) so offL+O_ reads at l==K-1
// (frac==0 there) stay in bounds and contribute exactly 0.
__device__ float  g_csT[(size_t)I_ * K_ * O_ + O_]; // [i][k][o], scale folded (32 MB)
__device__ float2 g_meta[B_ * I_];                  // {offL bits, frac}
__device__ float  g_silu[B_ * I_];                  // silu(tanh(x)), row-major (b,i)
__device__ float  g_part[ISPLIT + 1][B_ * O_];      // spline partials + base slot (5 MB)

// ---------------------------------------------------------------------------
// Pack: per (b,i) compute tanh/silu/bin/frac and absolute gather offset.
// ---------------------------------------------------------------------------
__global__ void pack_kernel(const float* __restrict__ x) {
    int t = blockIdx.x * blockDim.x + threadIdx.x;
    if (t >= B_ * I_) return;
    int i = t & (I_ - 1);

    float xv = x[t];
    float p = tanhf(xv);
    float silu = p / (1.0f + expf(-p));
    float c = fminf(fmaxf(p, -1.0f), 1.0f);
    const float step = 2.0f / 127.0f;
    float scaled = (c + 1.0f) / step;
    int l = (int)floorf(scaled);
    l = max(0, min(l, K_ - 1));
    float frac = scaled - (float)l;

    int offL = i * (K_ * O_) + l * O_;

    float2 m;
    m.x = __int_as_float(offL);
    m.y = frac;
    g_meta[t] = m;
    g_silu[t] = silu;
}

// ---------------------------------------------------------------------------
// Transpose coeff (O,I,K) -> csT (I,K,O), folding in spline_scale[o,i].
// float4 reads along k. block (8,32): tx -> k-quad, ty -> o within 32-tile.
// grid (K/32, O/32, I)
// ---------------------------------------------------------------------------
__global__ void transpose_coeff_kernel(const float* __restrict__ coeff,
                                       const float* __restrict__ scale) {
    __shared__ float tile[32][33];
    int i  = blockIdx.z;
    int k0 = blockIdx.x * 32;
    int o0 = blockIdx.y * 32;
    int tx = threadIdx.x;   // 0..7
    int ty = threadIdx.y;   // 0..31

    int o = o0 + ty;
    float s = scale[o * I_ + i];
    const float4* src = (const float4*)&coeff[(size_t)o * (I_ * K_) + i * K_ + k0];
    float4 v = src[tx];
    tile[ty][tx * 4 + 0] = v.x * s;
    tile[ty][tx * 4 + 1] = v.y * s;
    tile[ty][tx * 4 + 2] = v.z * s;
    tile[ty][tx * 4 + 3] = v.w * s;
    __syncthreads();

    int k = k0 + ty;
    float4 w;
    w.x = tile[tx * 4 + 0][ty];
    w.y = tile[tx * 4 + 1][ty];
    w.z = tile[tx * 4 + 2][ty];
    w.w = tile[tx * 4 + 3][ty];
    *(float4*)&g_csT[(size_t)i * (K_ * O_) + k * O_ + o0 + tx * 4] = w;
}

// ---------------------------------------------------------------------------
// Base GEMM: g_part[ISPLIT][b,o] = sum_i silu[b,i] * w[o,i].
// 64x64 output tile per CTA, K-tiles of 16. block 256, grid (B/64, O/64).
// ---------------------------------------------------------------------------
__global__ __launch_bounds__(256) void base_gemm_kernel(const float* __restrict__ w) {
    __shared__ float a_s[64][17];
    __shared__ float w_s[64][17];
    int b0 = blockIdx.x * 64;
    int o0 = blockIdx.y * 64;
    int t  = threadIdx.x;        // 0..255
    int tx = t & 15;             // o micro-tile
    int ty = t >> 4;             // b micro-tile
    int lrow = t >> 2;           // 0..63 load row
    int lq   = t & 3;            // 0..3  load quad

    float c[4][4];
#pragma unroll
    for (int r = 0; r < 4; r++)
#pragma unroll
        for (int q = 0; q < 4; q++) c[r][q] = 0.0f;

    for (int kt = 0; kt < I_; kt += 16) {
        float4 av = *(const float4*)&g_silu[(b0 + lrow) * I_ + kt + lq * 4];
        a_s[lrow][lq * 4 + 0] = av.x;
        a_s[lrow][lq * 4 + 1] = av.y;
        a_s[lrow][lq * 4 + 2] = av.z;
        a_s[lrow][lq * 4 + 3] = av.w;
        float4 wv = *(const float4*)&w[(o0 + lrow) * I_ + kt + lq * 4];
        w_s[lrow][lq * 4 + 0] = wv.x;
        w_s[lrow][lq * 4 + 1] = wv.y;
        w_s[lrow][lq * 4 + 2] = wv.z;
        w_s[lrow][lq * 4 + 3] = wv.w;
        __syncthreads();

#pragma unroll
        for (int k = 0; k < 16; k++) {
            float ar[4], wr[4];
#pragma unroll
            for (int r = 0; r < 4; r++) ar[r] = a_s[ty * 4 + r][k];
#pragma unroll
            for (int q = 0; q < 4; q++) wr[q] = w_s[tx * 4 + q][k];
#pragma unroll
            for (int r = 0; r < 4; r++)
#pragma unroll
                for (int q = 0; q < 4; q++) c[r][q] = fmaf(ar[r], wr[q], c[r][q]);
        }
        __syncthreads();
    }

#pragma unroll
    for (int r = 0; r < 4; r++) {
        float4 v = make_float4(c[r][0], c[r][1], c[r][2], c[r][3]);
        *(float4*)&g_part[ISPLIT][(b0 + ty * 4 + r) * O_ + o0 + tx * 4] = v;
    }
}

// ---------------------------------------------------------------------------
// Main spline kernel: float4 over o. block (64,4): tx -> o-quad, ty -> b row.
// grid (B/BT, ISPLIT). Per i-step: 1x LDS.64 + 2x LDG.128 + 8 FMA-class ops.
// ---------------------------------------------------------------------------
__global__ __launch_bounds__(256) void kan_main_kernel() {
    __shared__ float2 smeta[BT][ICHUNK];   // 2 KB

    int b0 = blockIdx.x * BT;
    int i0 = blockIdx.y * ICHUNK;
    int tx = threadIdx.x;                  // 0..63
    int ty = threadIdx.y;                  // 0..3
    int o4 = tx * 4;

    {
        int t = ty * 64 + tx;              // 0..255 -> one meta each
        int bb = t >> 6;
        int ii = t & (ICHUNK - 1);
        smeta[bb][ii] = g_meta[(b0 + bb) * I_ + i0 + ii];
    }
    __syncthreads();

    float4 acc = make_float4(0.f, 0.f, 0.f, 0.f);

#pragma unroll 2
    for (int i = 0; i < ICHUNK; i++) {
        float2 m = smeta[ty][i];
        int off = __float_as_int(m.x) + o4;
        float4 cL = *(const float4*)&g_csT[off];
        float4 cR = *(const float4*)&g_csT[off + O_];   // padded-safe at l==K-1
        float f = m.y;
        acc.x = fmaf(f, cR.x - cL.x, acc.x + cL.x);
        acc.y = fmaf(f, cR.y - cL.y, acc.y + cL.y);
        acc.z = fmaf(f, cR.z - cL.z, acc.z + cL.z);
        acc.w = fmaf(f, cR.w - cL.w, acc.w + cL.w);
    }

    *(float4*)&g_part[blockIdx.y][(b0 + ty) * O_ + o4] = acc;
}

// ---------------------------------------------------------------------------
// Reduce: out[b,o] = bias[o] + sum_{s<=ISPLIT} part[s][b,o]. Deterministic.
// ---------------------------------------------------------------------------
__global__ __launch_bounds__(256) void reduce_kernel(const float* __restrict__ bias,
                                                     float* __restrict__ out) {
    int q = blockIdx.x * 256 + threadIdx.x;       // float4 index in [0, B*O/4)
    int o4 = (q * 4) & (O_ - 1);
    float4 s = *(const float4*)&bias[o4];
#pragma unroll
    for (int p = 0; p <= ISPLIT; p++) {
        float4 v = *(const float4*)&g_part[p][q * 4];
        s.x += v.x; s.y += v.y; s.z += v.z; s.w += v.w;
    }
    *(float4*)&out[q * 4] = s;
}

// ---------------------------------------------------------------------------
// kernel_launch: graph-capturable, allocation-free, default stream.
// Inputs (metadata order): x, base_weight, spline_coefficients, spline_scale, bias
// ---------------------------------------------------------------------------
extern "C" void kernel_launch(void* const* d_in, const int* in_sizes, int n_in,
                              void* d_out, int out_size) {
    const float* x     = (const float*)d_in[0];
    const float* w     = (const float*)d_in[1];
    const float* coeff = (const float*)d_in[2];
    const float* scale = (const float*)d_in[3];
    const float* bias  = (const float*)d_in[4];
    float* out = (float*)d_out;

    pack_kernel<<<(B_ * I_ + 255) / 256, 256>>>(x);
    transpose_coeff_kernel<<<dim3(K_ / 32, O_ / 32, I_), dim3(8, 32)>>>(coeff, scale);
    base_gemm_kernel<<<dim3(B_ / 64, O_ / 64), 256>>>(w);
    kan_main_kernel<<<dim3(B_ / BT, ISPLIT), dim3(64, 4)>>>();
    reduce_kernel<<<(B_ * O_) / 1024, 256>>>(bias, out);
}

// round 15
// speedup vs baseline: 2.5160x; 1.2005x over previous
#include <cuda_runtime.h>
#include <cuda_fp16.h>
#include <math.h>

#define B_ 1024
#define I_ 256
#define O_ 256
#define K_ 128
#define BT 4          // batch rows per CTA in main kernel
#define ISPLIT 4      // i-dimension split factor
#define ICHUNK (I_ / ISPLIT)   // 64 i-values per CTA
#define KSPLIT 2      // k-split for base gemm
#define NPLANES (ISPLIT + KSPLIT)

// Static device scratch (allocation-free rule: __device__ globals only).
// g_csT_h padded by O_ halves (zero-initialized) so offL+O_ reads at l==K-1
// (frac==0 there) stay in bounds and contribute exactly 0.
__device__ __half  g_csT_h[(size_t)I_ * K_ * O_ + O_]; // [i][k][o] fp16, scale folded (16 MB)
__device__ float2  g_meta[B_ * I_];                    // {offL bits, frac}
__device__ float   g_silu[B_ * I_];                    // silu(tanh(x)), row-major (b,i)
__device__ float   g_part[NPLANES][B_ * O_];           // spline partials + base k-slices (6 MB)

// ---------------------------------------------------------------------------
// Pack: per (b,i) compute tanh/silu/bin/frac and absolute gather offset.
// ---------------------------------------------------------------------------
__global__ void pack_kernel(const float* __restrict__ x) {
    int t = blockIdx.x * blockDim.x + threadIdx.x;
    if (t >= B_ * I_) return;
    int i = t & (I_ - 1);

    float xv = x[t];
    float p = tanhf(xv);
    float silu = p / (1.0f + expf(-p));
    float c = fminf(fmaxf(p, -1.0f), 1.0f);
    const float step = 2.0f / 127.0f;
    float scaled = (c + 1.0f) / step;
    int l = (int)floorf(scaled);
    l = max(0, min(l, K_ - 1));
    float frac = scaled - (float)l;

    int offL = i * (K_ * O_) + l * O_;

    float2 m;
    m.x = __int_as_float(offL);
    m.y = frac;
    g_meta[t] = m;
    g_silu[t] = silu;
}

// ---------------------------------------------------------------------------
// Transpose coeff (O,I,K) -> csT (I,K,O) in fp16, folding in spline_scale[o,i].
// float4 reads along k. block (8,32): tx -> k-quad, ty -> o within 32-tile.
// grid (K/32, O/32, I)
// ---------------------------------------------------------------------------
__global__ void transpose_coeff_kernel(const float* __restrict__ coeff,
                                       const float* __restrict__ scale) {
    __shared__ float tile[32][33];
    int i  = blockIdx.z;
    int k0 = blockIdx.x * 32;
    int o0 = blockIdx.y * 32;
    int tx = threadIdx.x;   // 0..7
    int ty = threadIdx.y;   // 0..31

    int o = o0 + ty;
    float s = scale[o * I_ + i];
    const float4* src = (const float4*)&coeff[(size_t)o * (I_ * K_) + i * K_ + k0];
    float4 v = src[tx];
    tile[ty][tx * 4 + 0] = v.x * s;
    tile[ty][tx * 4 + 1] = v.y * s;
    tile[ty][tx * 4 + 2] = v.z * s;
    tile[ty][tx * 4 + 3] = v.w * s;
    __syncthreads();

    int k = k0 + ty;
    __half2 h01 = __floats2half2_rn(tile[tx * 4 + 0][ty], tile[tx * 4 + 1][ty]);
    __half2 h23 = __floats2half2_rn(tile[tx * 4 + 2][ty], tile[tx * 4 + 3][ty]);
    uint2 pk;
    pk.x = reinterpret_cast<unsigned&>(h01);
    pk.y = reinterpret_cast<unsigned&>(h23);
    *(uint2*)&g_csT_h[(size_t)i * (K_ * O_) + k * O_ + o0 + tx * 4] = pk;
}

// ---------------------------------------------------------------------------
// Base GEMM (k-split): g_part[ISPLIT+kz][b,o] = sum_{i in kz-half} silu[b,i]*w[o,i].
// 64x64 output tile, K-tiles of 16. block 256, grid (B/64, O/64, KSPLIT).
// ---------------------------------------------------------------------------
__global__ __launch_bounds__(256) void base_gemm_kernel(const float* __restrict__ w) {
    __shared__ float a_s[64][17];
    __shared__ float w_s[64][17];
    int b0 = blockIdx.x * 64;
    int o0 = blockIdx.y * 64;
    int kz = blockIdx.z;
    int t  = threadIdx.x;        // 0..255
    int tx = t & 15;             // o micro-tile
    int ty = t >> 4;             // b micro-tile
    int lrow = t >> 2;           // 0..63 load row
    int lq   = t & 3;            // 0..3  load quad

    float c[4][4];
#pragma unroll
    for (int r = 0; r < 4; r++)
#pragma unroll
        for (int q = 0; q < 4; q++) c[r][q] = 0.0f;

    int kbeg = kz * (I_ / KSPLIT);
    int kend = kbeg + (I_ / KSPLIT);
    for (int kt = kbeg; kt < kend; kt += 16) {
        float4 av = *(const float4*)&g_silu[(b0 + lrow) * I_ + kt + lq * 4];
        a_s[lrow][lq * 4 + 0] = av.x;
        a_s[lrow][lq * 4 + 1] = av.y;
        a_s[lrow][lq * 4 + 2] = av.z;
        a_s[lrow][lq * 4 + 3] = av.w;
        float4 wv = *(const float4*)&w[(o0 + lrow) * I_ + kt + lq * 4];
        w_s[lrow][lq * 4 + 0] = wv.x;
        w_s[lrow][lq * 4 + 1] = wv.y;
        w_s[lrow][lq * 4 + 2] = wv.z;
        w_s[lrow][lq * 4 + 3] = wv.w;
        __syncthreads();

#pragma unroll
        for (int k = 0; k < 16; k++) {
            float ar[4], wr[4];
#pragma unroll
            for (int r = 0; r < 4; r++) ar[r] = a_s[ty * 4 + r][k];
#pragma unroll
            for (int q = 0; q < 4; q++) wr[q] = w_s[tx * 4 + q][k];
#pragma unroll
            for (int r = 0; r < 4; r++)
#pragma unroll
                for (int q = 0; q < 4; q++) c[r][q] = fmaf(ar[r], wr[q], c[r][q]);
        }
        __syncthreads();
    }

#pragma unroll
    for (int r = 0; r < 4; r++) {
        float4 v = make_float4(c[r][0], c[r][1], c[r][2], c[r][3]);
        *(float4*)&g_part[ISPLIT + kz][(b0 + ty * 4 + r) * O_ + o0 + tx * 4] = v;
    }
}

// ---------------------------------------------------------------------------
// Main spline kernel: fp16 gathers, fp32 accumulate. block (64,4): tx -> o-quad,
// ty -> b row. grid (B/BT, ISPLIT). Per i-step: 1x LDS.64 + 2x LDG.64 + cvt + FMA.
// ---------------------------------------------------------------------------
__global__ __launch_bounds__(256) void kan_main_kernel() {
    __shared__ float2 smeta[BT][ICHUNK];   // 2 KB

    int b0 = blockIdx.x * BT;
    int i0 = blockIdx.y * ICHUNK;
    int tx = threadIdx.x;                  // 0..63
    int ty = threadIdx.y;                  // 0..3
    int o4 = tx * 4;

    {
        int t = ty * 64 + tx;              // 0..255 -> one meta each
        int bb = t >> 6;
        int ii = t & (ICHUNK - 1);
        smeta[bb][ii] = g_meta[(b0 + bb) * I_ + i0 + ii];
    }
    __syncthreads();

    float4 acc = make_float4(0.f, 0.f, 0.f, 0.f);

#pragma unroll 2
    for (int i = 0; i < ICHUNK; i++) {
        float2 m = smeta[ty][i];
        int off = __float_as_int(m.x) + o4;
        uint2 rl = *(const uint2*)&g_csT_h[off];        // 4 halves (cL)
        uint2 rr = *(const uint2*)&g_csT_h[off + O_];   // 4 halves (cR), padded-safe
        float2 l01 = __half22float2(reinterpret_cast<__half2&>(rl.x));
        float2 l23 = __half22float2(reinterpret_cast<__half2&>(rl.y));
        float2 r01 = __half22float2(reinterpret_cast<__half2&>(rr.x));
        float2 r23 = __half22float2(reinterpret_cast<__half2&>(rr.y));
        float f = m.y;
        acc.x = fmaf(f, r01.x - l01.x, acc.x + l01.x);
        acc.y = fmaf(f, r01.y - l01.y, acc.y + l01.y);
        acc.z = fmaf(f, r23.x - l23.x, acc.z + l23.x);
        acc.w = fmaf(f, r23.y - l23.y, acc.w + l23.y);
    }

    *(float4*)&g_part[blockIdx.y][(b0 + ty) * O_ + o4] = acc;
}

// ---------------------------------------------------------------------------
// Reduce: out[b,o] = bias[o] + sum_{p<NPLANES} part[p][b,o]. Deterministic.
// ---------------------------------------------------------------------------
__global__ __launch_bounds__(256) void reduce_kernel(const float* __restrict__ bias,
                                                     float* __restrict__ out) {
    int q = blockIdx.x * 256 + threadIdx.x;       // float4 index in [0, B*O/4)
    int o4 = (q * 4) & (O_ - 1);
    float4 s = *(const float4*)&bias[o4];
#pragma unroll
    for (int p = 0; p < NPLANES; p++) {
        float4 v = *(const float4*)&g_part[p][q * 4];
        s.x += v.x; s.y += v.y; s.z += v.z; s.w += v.w;
    }
    *(float4*)&out[q * 4] = s;
}

// ---------------------------------------------------------------------------
// kernel_launch: graph-capturable, allocation-free, default stream.
// Inputs (metadata order): x, base_weight, spline_coefficients, spline_scale, bias
// ---------------------------------------------------------------------------
extern "C" void kernel_launch(void* const* d_in, const int* in_sizes, int n_in,
                              void* d_out, int out_size) {
    const float* x     = (const float*)d_in[0];
    const float* w     = (const float*)d_in[1];
    const float* coeff = (const float*)d_in[2];
    const float* scale = (const float*)d_in[3];
    const float* bias  = (const float*)d_in[4];
    float* out = (float*)d_out;

    pack_kernel<<<(B_ * I_ + 255) / 256, 256>>>(x);
    transpose_coeff_kernel<<<dim3(K_ / 32, O_ / 32, I_), dim3(8, 32)>>>(coeff, scale);
    base_gemm_kernel<<<dim3(B_ / 64, O_ / 64, KSPLIT), 256>>>(w);
    kan_main_kernel<<<dim3(B_ / BT, ISPLIT), dim3(64, 4)>>>();
    reduce_kernel<<<(B_ * O_) / 1024, 256>>>(bias, out);
}